// round 3
// baseline (speedup 1.0000x reference)
#include <cuda_runtime.h>
#include <cstdint>

#define B_    2
#define S_    2048
#define H_    16
#define DH_   64
#define DHID_ 256
#define DKER_ 64
#define D_    1024
#define BH_   (B_*H_)

// Scratch (static device globals — allowed; no runtime allocation)
__device__ float g_t1q[BH_*S_*DHID_];   // 64 MB
__device__ float g_t1k[BH_*S_*DHID_];   // 64 MB
__device__ float g_qf [BH_*S_*DKER_];   // 16 MB  (|qf|)
__device__ float g_kf [BH_*S_*DKER_];   // 16 MB  (|kf|)
__device__ int     g_mask_mode;
__device__ uint8_t g_mask[B_*S_*S_];    // 8.4 MB normalized mask

__device__ __forceinline__ float to_tf32(float x) {
    uint32_t u;
    asm("cvt.rna.tf32.f32 %0, %1;" : "=r"(u) : "f"(x));
    return __uint_as_float(u);
}

// jax.nn.gelu default: approximate=True (tanh form)
__device__ __forceinline__ float gelu_t(float x) {
    float x3 = x * x * x;
    float t  = tanhf(0.7978845608028654f * (x + 0.044715f * x3));
    return 0.5f * x * (1.0f + t);
}

__device__ __forceinline__ void mma_tf32(float* c, const float* a, const float* b) {
    asm volatile(
        "mma.sync.aligned.m16n8k8.row.col.f32.tf32.tf32.f32 "
        "{%0,%1,%2,%3}, {%4,%5,%6,%7}, {%8,%9}, {%0,%1,%2,%3};\n"
        : "+f"(c[0]), "+f"(c[1]), "+f"(c[2]), "+f"(c[3])
        : "r"(__float_as_uint(a[0])), "r"(__float_as_uint(a[1])),
          "r"(__float_as_uint(a[2])), "r"(__float_as_uint(a[3])),
          "r"(__float_as_uint(b[0])), "r"(__float_as_uint(b[1])));
}

// ---------------------------------------------------------------------------
// Mask dtype detection + normalization.
// bernoulli -> bool in JAX; harness may ship it as uint8, int32 or float32.
// Values are only 0/1 (or 0.0f/1.0f), so the bit patterns disambiguate:
//   word == 0x3f800000           -> float32
//   word  > 1 (and not above)    -> packed uint8 bytes
//   all sampled words in {0,1}   -> int32
// ---------------------------------------------------------------------------
__global__ void detect_mask_kernel(const uint32_t* __restrict__ m) {
    if (threadIdx.x == 0 && blockIdx.x == 0) {
        int mode = 1;  // int32 default
        for (int i = 0; i < 1024; i++) {
            uint32_t w = m[(size_t)i * 2048];   // spread over first 2M words
            if (w == 0x3f800000u) { mode = 2; break; }
            if (w > 1u)           { mode = 0; break; }
        }
        g_mask_mode = mode;
    }
}

__global__ __launch_bounds__(1024, 2)
void convert_mask_kernel(const void* __restrict__ m) {
    size_t idx = (size_t)blockIdx.x * 1024 + threadIdx.x;
    int mode = g_mask_mode;
    uint8_t v;
    if (mode == 0)      v = ((const uint8_t*) m)[idx] != 0;
    else if (mode == 1) v = ((const uint32_t*)m)[idx] != 0u;
    else                v = ((const float*)   m)[idx] != 0.0f;
    g_mask[idx] = v;
}

// ---------------------------------------------------------------------------
// Layer 1: T1[bh,s,e] = gelu( sum_d X[b,s,h*64+d] * W[h,d,e] )
// CTA tile 128(M) x 128(N), K=64.  8 warps as 4(m) x 2(n), warp tile 32x64.
// ---------------------------------------------------------------------------
__global__ __launch_bounds__(256, 1)
void layer1_kernel(const float* __restrict__ X, const float* __restrict__ W,
                   float* __restrict__ T1) {
    extern __shared__ float sm[];
    float* As = sm;               // [128][68]  (m x k)
    float* Bs = sm + 128*68;      // [128][68]  (n x k)
    int bh = blockIdx.z, b = bh >> 4, h = bh & 15;
    int m0 = blockIdx.x * 128, n0 = blockIdx.y * 128;
    int tid = threadIdx.x;

    const float* Xb = X + ((size_t)(b*S_ + m0))*D_ + h*DH_;
    for (int idx = tid; idx < 128*64; idx += 256) {
        int r = idx >> 6, d = idx & 63;
        As[r*68 + d] = to_tf32(Xb[(size_t)r*D_ + d]);
    }
    const float* Wh = W + (size_t)h*DH_*DHID_ + n0;
    for (int idx = tid; idx < 64*128; idx += 256) {
        int k = idx >> 7, n = idx & 127;
        Bs[n*68 + k] = to_tf32(Wh[(size_t)k*DHID_ + n]);
    }
    __syncthreads();

    int warp = tid >> 5, lane = tid & 31, g = lane >> 2, tg = lane & 3;
    int wm = warp & 3, wn = warp >> 2;
    float acc[2][8][4];
    #pragma unroll
    for (int i=0;i<2;i++) for (int j=0;j<8;j++) for (int c=0;c<4;c++) acc[i][j][c]=0.f;

    #pragma unroll
    for (int k0 = 0; k0 < 64; k0 += 8) {
        float a[2][4], bf[8][2];
        #pragma unroll
        for (int i=0;i<2;i++) {
            int rb = wm*32 + i*16;
            a[i][0] = As[(rb+g  )*68 + k0+tg  ];
            a[i][1] = As[(rb+g+8)*68 + k0+tg  ];
            a[i][2] = As[(rb+g  )*68 + k0+tg+4];
            a[i][3] = As[(rb+g+8)*68 + k0+tg+4];
        }
        #pragma unroll
        for (int j=0;j<8;j++) {
            int nb = wn*64 + j*8 + g;
            bf[j][0] = Bs[nb*68 + k0+tg  ];
            bf[j][1] = Bs[nb*68 + k0+tg+4];
        }
        #pragma unroll
        for (int i=0;i<2;i++)
            #pragma unroll
            for (int j=0;j<8;j++)
                mma_tf32(acc[i][j], a[i], bf[j]);
    }

    float* T1b = T1 + ((size_t)bh*S_ + m0)*DHID_ + n0;
    #pragma unroll
    for (int i=0;i<2;i++) {
        #pragma unroll
        for (int j=0;j<8;j++) {
            int rr = wm*32 + i*16 + g;
            int cc = wn*64 + j*8 + 2*tg;
            *(float2*)&T1b[(size_t)rr*DHID_ + cc] =
                make_float2(gelu_t(acc[i][j][0]), gelu_t(acc[i][j][1]));
            *(float2*)&T1b[(size_t)(rr+8)*DHID_ + cc] =
                make_float2(gelu_t(acc[i][j][2]), gelu_t(acc[i][j][3]));
        }
    }
}

// ---------------------------------------------------------------------------
// Layer 2 (q): qf = |gelu(T1q @ Wq2)|   M tile 128, N=64, K=256
// ---------------------------------------------------------------------------
__global__ __launch_bounds__(256, 1)
void layer2q_kernel(const float* __restrict__ W2) {
    extern __shared__ float sm[];
    float* As = sm;               // [128][68]
    float* Bs = sm + 128*68;      // [64][68]
    int bh = blockIdx.z, h = bh & 15;
    int m0 = blockIdx.x * 128;
    int tid = threadIdx.x;
    int warp = tid>>5, lane = tid&31, g = lane>>2, tg = lane&3;

    float acc[8][4];
    #pragma unroll
    for (int j=0;j<8;j++) for (int c=0;c<4;c++) acc[j][c]=0.f;

    const float* T1 = g_t1q + ((size_t)bh*S_ + m0)*DHID_;
    const float* Wh = W2 + (size_t)h*DHID_*DKER_;

    for (int kt = 0; kt < 4; kt++) {
        for (int idx = tid; idx < 128*64; idx += 256) {
            int r = idx>>6, k = idx&63;
            As[r*68 + k] = to_tf32(T1[(size_t)r*DHID_ + kt*64 + k]);
        }
        for (int idx = tid; idx < 64*64; idx += 256) {
            int k = idx>>6, n = idx&63;
            Bs[n*68 + k] = to_tf32(Wh[(size_t)(kt*64 + k)*DKER_ + n]);
        }
        __syncthreads();
        #pragma unroll
        for (int k0=0;k0<64;k0+=8) {
            float a[4], bf[8][2];
            int rb = warp*16;
            a[0] = As[(rb+g  )*68 + k0+tg  ];
            a[1] = As[(rb+g+8)*68 + k0+tg  ];
            a[2] = As[(rb+g  )*68 + k0+tg+4];
            a[3] = As[(rb+g+8)*68 + k0+tg+4];
            #pragma unroll
            for (int j=0;j<8;j++) {
                int nb = j*8+g;
                bf[j][0] = Bs[nb*68 + k0+tg  ];
                bf[j][1] = Bs[nb*68 + k0+tg+4];
            }
            #pragma unroll
            for (int j=0;j<8;j++) mma_tf32(acc[j], a, bf[j]);
        }
        __syncthreads();
    }
    float* outp = g_qf + ((size_t)bh*S_ + m0)*DKER_;
    #pragma unroll
    for (int j=0;j<8;j++) {
        int rr = warp*16 + g, cc = j*8 + 2*tg;
        *(float2*)&outp[(size_t)rr*DKER_ + cc] =
            make_float2(fabsf(gelu_t(acc[j][0])), fabsf(gelu_t(acc[j][1])));
        *(float2*)&outp[(size_t)(rr+8)*DKER_ + cc] =
            make_float2(fabsf(gelu_t(acc[j][2])), fabsf(gelu_t(acc[j][3])));
    }
}

// ---------------------------------------------------------------------------
// Layer 2 (k): tmp = |sD| * gelu(T1k @ Wk2);  kf = |tmp + (tmp @ Wint)*sD2|
// ---------------------------------------------------------------------------
__global__ __launch_bounds__(256, 1)
void layer2k_kernel(const float* __restrict__ W2, const float* __restrict__ Wint,
                    const float* __restrict__ sD, const float* __restrict__ sD2) {
    extern __shared__ float sm[];
    float* As = sm;                 // [128][68]
    float* Bs = sm + 128*68;        // [64][68]
    float* Ts = Bs + 64*68;         // [128][68]  tmp tile
    int bh = blockIdx.z, h = bh & 15;
    int m0 = blockIdx.x * 128;
    int tid = threadIdx.x;
    int warp = tid>>5, lane = tid&31, g = lane>>2, tg = lane&3;

    float acc[8][4];
    #pragma unroll
    for (int j=0;j<8;j++) for (int c=0;c<4;c++) acc[j][c]=0.f;

    const float* T1 = g_t1k + ((size_t)bh*S_ + m0)*DHID_;
    const float* Wh = W2 + (size_t)h*DHID_*DKER_;

    for (int kt = 0; kt < 4; kt++) {
        for (int idx = tid; idx < 128*64; idx += 256) {
            int r = idx>>6, k = idx&63;
            As[r*68 + k] = to_tf32(T1[(size_t)r*DHID_ + kt*64 + k]);
        }
        for (int idx = tid; idx < 64*64; idx += 256) {
            int k = idx>>6, n = idx&63;
            Bs[n*68 + k] = to_tf32(Wh[(size_t)(kt*64 + k)*DKER_ + n]);
        }
        __syncthreads();
        #pragma unroll
        for (int k0=0;k0<64;k0+=8) {
            float a[4], bf[8][2];
            int rb = warp*16;
            a[0] = As[(rb+g  )*68 + k0+tg  ];
            a[1] = As[(rb+g+8)*68 + k0+tg  ];
            a[2] = As[(rb+g  )*68 + k0+tg+4];
            a[3] = As[(rb+g+8)*68 + k0+tg+4];
            #pragma unroll
            for (int j=0;j<8;j++) {
                int nb = j*8+g;
                bf[j][0] = Bs[nb*68 + k0+tg  ];
                bf[j][1] = Bs[nb*68 + k0+tg+4];
            }
            #pragma unroll
            for (int j=0;j<8;j++) mma_tf32(acc[j], a, bf[j]);
        }
        __syncthreads();
    }

    const float* sDh  = sD  + h*DKER_;
    const float* sD2h = sD2 + h*DKER_;
    // tmp into smem
    #pragma unroll
    for (int j=0;j<8;j++) {
        int rr = warp*16 + g, cc = j*8 + 2*tg;
        Ts[(size_t)rr*68 + cc  ]   = fabsf(sDh[cc  ]) * gelu_t(acc[j][0]);
        Ts[(size_t)rr*68 + cc+1]   = fabsf(sDh[cc+1]) * gelu_t(acc[j][1]);
        Ts[(size_t)(rr+8)*68 + cc  ] = fabsf(sDh[cc  ]) * gelu_t(acc[j][2]);
        Ts[(size_t)(rr+8)*68 + cc+1] = fabsf(sDh[cc+1]) * gelu_t(acc[j][3]);
    }
    __syncthreads();
    // Wint into Bs (transposed)
    for (int idx = tid; idx < 64*64; idx += 256) {
        int k = idx>>6, n = idx&63;
        Bs[n*68 + k] = to_tf32(Wint[(size_t)h*DKER_*DKER_ + (size_t)k*DKER_ + n]);
    }
    __syncthreads();

    float ac2[8][4];
    #pragma unroll
    for (int j=0;j<8;j++) for (int c=0;c<4;c++) ac2[j][c]=0.f;
    #pragma unroll
    for (int k0=0;k0<64;k0+=8) {
        float a[4], bf[8][2];
        int rb = warp*16;
        a[0] = to_tf32(Ts[(rb+g  )*68 + k0+tg  ]);
        a[1] = to_tf32(Ts[(rb+g+8)*68 + k0+tg  ]);
        a[2] = to_tf32(Ts[(rb+g  )*68 + k0+tg+4]);
        a[3] = to_tf32(Ts[(rb+g+8)*68 + k0+tg+4]);
        #pragma unroll
        for (int j=0;j<8;j++) {
            int nb = j*8+g;
            bf[j][0] = Bs[nb*68 + k0+tg  ];
            bf[j][1] = Bs[nb*68 + k0+tg+4];
        }
        #pragma unroll
        for (int j=0;j<8;j++) mma_tf32(ac2[j], a, bf[j]);
    }

    float* outp = g_kf + ((size_t)bh*S_ + m0)*DKER_;
    #pragma unroll
    for (int j=0;j<8;j++) {
        int rr = warp*16 + g, cc = j*8 + 2*tg;
        float t00 = Ts[(size_t)rr*68 + cc  ],   t01 = Ts[(size_t)rr*68 + cc+1];
        float t10 = Ts[(size_t)(rr+8)*68 + cc], t11 = Ts[(size_t)(rr+8)*68 + cc+1];
        *(float2*)&outp[(size_t)rr*DKER_ + cc] =
            make_float2(fabsf(t00 + ac2[j][0]*sD2h[cc  ]),
                        fabsf(t01 + ac2[j][1]*sD2h[cc+1]));
        *(float2*)&outp[(size_t)(rr+8)*DKER_ + cc] =
            make_float2(fabsf(t10 + ac2[j][2]*sD2h[cc  ]),
                        fabsf(t11 + ac2[j][3]*sD2h[cc+1]));
    }
}

// ---------------------------------------------------------------------------
// Attention: per (bh, 128-row q tile), stream over t in 128-tiles.
// num = mask ? score+1e-6 : exp(saw);  rowsum += mask ? score : 0
// o = (num @ v) / (rowsum + 1e-6 + exp(sp_lse))
// ---------------------------------------------------------------------------
__global__ __launch_bounds__(256, 1)
void attn_kernel(const float* __restrict__ Vg,
                 const float* __restrict__ sp_lse, const float* __restrict__ saw,
                 float* __restrict__ outp) {
    extern __shared__ float sm[];
    float* Qs = sm;                  // [128][68]
    float* Ks = Qs + 128*68;         // [128][68]
    float* Vs = Ks + 128*68;         // [128][72]
    float* Ps = Vs + 128*72;         // [128][132]
    float* rowsum = Ps + 128*132;    // [128]
    int bh = blockIdx.y, b = bh >> 4, h = bh & 15;
    int m0 = blockIdx.x * 128;
    int tid = threadIdx.x, warp = tid>>5, lane = tid&31, g = lane>>2, tg = lane&3;
    int wm = warp & 3, wn = warp >> 2;

    const float* qf = g_qf + ((size_t)bh*S_ + m0)*DKER_;
    for (int idx = tid; idx < 128*64; idx += 256) {
        int r = idx>>6, e = idx&63;
        Qs[r*68+e] = to_tf32(qf[(size_t)r*DKER_ + e]);
    }
    if (tid < 128) rowsum[tid] = 0.f;

    float oacc[8][4];
    #pragma unroll
    for (int j=0;j<8;j++) for (int c=0;c<4;c++) oacc[j][c]=0.f;
    float rs[2][2] = {{0.f,0.f},{0.f,0.f}};

    const uint8_t* mb  = g_mask + (size_t)b*S_*S_;
    const float* sawb  = saw   + (size_t)bh*S_*S_;
    __syncthreads();

    for (int t0 = 0; t0 < S_; t0 += 128) {
        const float* kf = g_kf + ((size_t)bh*S_ + t0)*DKER_;
        const float* vb = Vg + ((size_t)(b*S_ + t0))*D_ + h*DH_;
        for (int idx = tid; idx < 128*64; idx += 256) {
            int r = idx>>6, e = idx&63;
            Ks[r*68+e] = to_tf32(kf[(size_t)r*DKER_ + e]);
            Vs[r*72+e] = to_tf32(vb[(size_t)r*D_ + e]);
        }
        __syncthreads();

        float sacc[2][8][4];
        #pragma unroll
        for (int i=0;i<2;i++) for (int j=0;j<8;j++) for (int c=0;c<4;c++) sacc[i][j][c]=0.f;
        #pragma unroll
        for (int k0 = 0; k0 < 64; k0 += 8) {
            float a[2][4], bf[8][2];
            #pragma unroll
            for (int i=0;i<2;i++) {
                int rb = wm*32 + i*16;
                a[i][0] = Qs[(rb+g  )*68 + k0+tg  ];
                a[i][1] = Qs[(rb+g+8)*68 + k0+tg  ];
                a[i][2] = Qs[(rb+g  )*68 + k0+tg+4];
                a[i][3] = Qs[(rb+g+8)*68 + k0+tg+4];
            }
            #pragma unroll
            for (int j=0;j<8;j++) {
                int nb = wn*64 + j*8 + g;
                bf[j][0] = Ks[nb*68 + k0+tg  ];
                bf[j][1] = Ks[nb*68 + k0+tg+4];
            }
            #pragma unroll
            for (int i=0;i<2;i++)
                #pragma unroll
                for (int j=0;j<8;j++)
                    mma_tf32(sacc[i][j], a[i], bf[j]);
        }

        // epilogue: numerator + masked row sums, write P
        #pragma unroll
        for (int i=0;i<2;i++) {
            int rl = wm*32 + i*16 + g;
            #pragma unroll
            for (int j=0;j<8;j++) {
                int cl = wn*64 + j*8 + 2*tg;
                int sg0 = m0 + rl, sg1 = sg0 + 8, tgl = t0 + cl;
                {
                    const uint8_t* mp = mb + (size_t)sg0*S_ + tgl;
                    float2 sw = *(const float2*)(sawb + (size_t)sg0*S_ + tgl);
                    float n0v, n1v;
                    if (mp[0]) { n0v = sacc[i][j][0] + 1e-6f; rs[i][0] += sacc[i][j][0]; }
                    else         n0v = __expf(sw.x);
                    if (mp[1]) { n1v = sacc[i][j][1] + 1e-6f; rs[i][0] += sacc[i][j][1]; }
                    else         n1v = __expf(sw.y);
                    *(float2*)&Ps[rl*132 + cl] = make_float2(to_tf32(n0v), to_tf32(n1v));
                }
                {
                    const uint8_t* mp = mb + (size_t)sg1*S_ + tgl;
                    float2 sw = *(const float2*)(sawb + (size_t)sg1*S_ + tgl);
                    float n0v, n1v;
                    if (mp[0]) { n0v = sacc[i][j][2] + 1e-6f; rs[i][1] += sacc[i][j][2]; }
                    else         n0v = __expf(sw.x);
                    if (mp[1]) { n1v = sacc[i][j][3] + 1e-6f; rs[i][1] += sacc[i][j][3]; }
                    else         n1v = __expf(sw.y);
                    *(float2*)&Ps[(rl+8)*132 + cl] = make_float2(to_tf32(n0v), to_tf32(n1v));
                }
            }
        }
        __syncthreads();

        // o += P @ V  (warp w owns rows 16w..16w+15)
        #pragma unroll
        for (int k0 = 0; k0 < 128; k0 += 8) {
            float a[4], bf[8][2];
            int rb = warp*16;
            a[0] = Ps[(rb+g  )*132 + k0+tg  ];
            a[1] = Ps[(rb+g+8)*132 + k0+tg  ];
            a[2] = Ps[(rb+g  )*132 + k0+tg+4];
            a[3] = Ps[(rb+g+8)*132 + k0+tg+4];
            #pragma unroll
            for (int j=0;j<8;j++) {
                bf[j][0] = Vs[(k0+tg  )*72 + j*8+g];
                bf[j][1] = Vs[(k0+tg+4)*72 + j*8+g];
            }
            #pragma unroll
            for (int j=0;j<8;j++) mma_tf32(oacc[j], a, bf[j]);
        }
        __syncthreads();
    }

    // reduce masked row sums
    #pragma unroll
    for (int i=0;i<2;i++)
        #pragma unroll
        for (int p=0;p<2;p++) {
            float v = rs[i][p];
            v += __shfl_xor_sync(0xffffffffu, v, 1);
            v += __shfl_xor_sync(0xffffffffu, v, 2);
            if (tg == 0) atomicAdd(&rowsum[wm*32 + i*16 + g + 8*p], v);
        }
    __syncthreads();

    const float* spb = sp_lse + (size_t)bh*S_ + m0;
    float* ob = outp + ((size_t)(b*S_ + m0))*D_ + h*DH_;
    int r0 = warp*16 + g;
    float den0 = 1.0f / (rowsum[r0  ] + 1e-6f + __expf(spb[r0  ]));
    float den1 = 1.0f / (rowsum[r0+8] + 1e-6f + __expf(spb[r0+8]));
    #pragma unroll
    for (int j=0;j<8;j++) {
        int cc = j*8 + 2*tg;
        *(float2*)&ob[(size_t)r0*D_ + cc] =
            make_float2(oacc[j][0]*den0, oacc[j][1]*den0);
        *(float2*)&ob[(size_t)(r0+8)*D_ + cc] =
            make_float2(oacc[j][2]*den1, oacc[j][3]*den1);
    }
}

// ---------------------------------------------------------------------------
extern "C" void kernel_launch(void* const* d_in, const int* in_sizes, int n_in,
                              void* d_out, int out_size) {
    (void)in_sizes; (void)n_in; (void)out_size;
    const float*   q    = (const float*)d_in[1];
    const float*   k    = (const float*)d_in[2];
    const float*   v    = (const float*)d_in[3];
    const void*    mask = d_in[4];
    const float*   sp   = (const float*)d_in[5];
    const float*   saw  = (const float*)d_in[6];
    const float*   Wq1  = (const float*)d_in[8];
    const float*   Wk1  = (const float*)d_in[9];
    const float*   Wq2  = (const float*)d_in[10];
    const float*   Wk2  = (const float*)d_in[11];
    const float*   Wint = (const float*)d_in[12];
    const float*   sD   = (const float*)d_in[13];
    const float*   sD2  = (const float*)d_in[14];
    float* outp = (float*)d_out;

    const int SMEM1  = (128*68 + 128*68) * 4;                    // 69632
    const int SMEM2Q = (128*68 + 64*68) * 4;                     // 52224
    const int SMEM2K = (128*68 + 64*68 + 128*68) * 4;            // 87040
    const int SMEMA  = (128*68 + 128*68 + 128*72 + 128*132 + 128) * 4;  // 174592

    cudaFuncSetAttribute(layer1_kernel,  cudaFuncAttributeMaxDynamicSharedMemorySize, SMEM1);
    cudaFuncSetAttribute(layer2q_kernel, cudaFuncAttributeMaxDynamicSharedMemorySize, SMEM2Q);
    cudaFuncSetAttribute(layer2k_kernel, cudaFuncAttributeMaxDynamicSharedMemorySize, SMEM2K);
    cudaFuncSetAttribute(attn_kernel,    cudaFuncAttributeMaxDynamicSharedMemorySize, SMEMA);

    float* t1q; cudaGetSymbolAddress((void**)&t1q, g_t1q);
    float* t1k; cudaGetSymbolAddress((void**)&t1k, g_t1k);

    detect_mask_kernel<<<1, 32>>>((const uint32_t*)mask);
    convert_mask_kernel<<<8192, 1024>>>(mask);
    layer1_kernel<<<dim3(16, 2, BH_), 256, SMEM1>>>(q, Wq1, t1q);
    layer1_kernel<<<dim3(16, 2, BH_), 256, SMEM1>>>(k, Wk1, t1k);
    layer2q_kernel<<<dim3(16, 1, BH_), 256, SMEM2Q>>>(Wq2);
    layer2k_kernel<<<dim3(16, 1, BH_), 256, SMEM2K>>>(Wk2, Wint, sD, sD2);
    attn_kernel<<<dim3(16, BH_), 256, SMEMA>>>(v, sp, saw, outp);
}

// round 4
// speedup vs baseline: 1.6015x; 1.6015x over previous
#include <cuda_runtime.h>
#include <cstdint>

#define B_    2
#define S_    2048
#define H_    16
#define DH_   64
#define DHID_ 256
#define DKER_ 64
#define D_    1024
#define BH_   (B_*H_)

// Scratch (static device globals — allowed; no runtime allocation)
__device__ float    g_qf [BH_*S_*DKER_];        // 16 MB  (|qf|)
__device__ float    g_kf [BH_*S_*DKER_];        // 16 MB  (|kf|)
__device__ int      g_mask_mode;
__device__ uint32_t g_maskbits[B_*S_*S_/32];    // 1 MB bit-packed mask

__device__ __forceinline__ float to_tf32(float x) {
    uint32_t u;
    asm("cvt.rna.tf32.f32 %0, %1;" : "=r"(u) : "f"(x));
    return __uint_as_float(u);
}

// jax.nn.gelu default: approximate=True (tanh form)
__device__ __forceinline__ float gelu_t(float x) {
    float x3 = x * x * x;
    float t  = tanhf(0.7978845608028654f * (x + 0.044715f * x3));
    return 0.5f * x * (1.0f + t);
}

__device__ __forceinline__ void mma_tf32(float* c, const float* a, const float* b) {
    asm volatile(
        "mma.sync.aligned.m16n8k8.row.col.f32.tf32.tf32.f32 "
        "{%0,%1,%2,%3}, {%4,%5,%6,%7}, {%8,%9}, {%0,%1,%2,%3};\n"
        : "+f"(c[0]), "+f"(c[1]), "+f"(c[2]), "+f"(c[3])
        : "r"(__float_as_uint(a[0])), "r"(__float_as_uint(a[1])),
          "r"(__float_as_uint(a[2])), "r"(__float_as_uint(a[3])),
          "r"(__float_as_uint(b[0])), "r"(__float_as_uint(b[1])));
}

__device__ __forceinline__ uint32_t smaddr(const void* p) {
    return (uint32_t)__cvta_generic_to_shared(p);
}
#define CPA16(dst, src) \
    asm volatile("cp.async.cg.shared.global [%0], [%1], 16;\n" :: "r"(dst), "l"(src))
#define CPA_COMMIT() asm volatile("cp.async.commit_group;\n" ::: "memory")
#define CPA_WAIT(N)  asm volatile("cp.async.wait_group %0;\n" :: "n"(N) : "memory")

// ---------------------------------------------------------------------------
// Mask dtype detection (values only 0/1 so bit patterns disambiguate)
// ---------------------------------------------------------------------------
__global__ void detect_mask_kernel(const uint32_t* __restrict__ m) {
    if (threadIdx.x == 0 && blockIdx.x == 0) {
        int mode = 1;  // int32 default
        for (int i = 0; i < 1024; i++) {
            uint32_t w = m[(size_t)i * 2048];
            if (w == 0x3f800000u) { mode = 2; break; }
            if (w > 1u)           { mode = 0; break; }
        }
        g_mask_mode = mode;
    }
}

// Bit-pack mask: each warp handles 1024 consecutive elements -> 32 words.
__global__ __launch_bounds__(256)
void maskbits_kernel(const void* __restrict__ m) {
    int mode = g_mask_mode;
    int warpg = (blockIdx.x * 256 + threadIdx.x) >> 5;
    int lane  = threadIdx.x & 31;
    size_t base = (size_t)warpg * 1024;
    #pragma unroll 4
    for (int s = 0; s < 32; s++) {
        size_t idx = base + (size_t)s * 32 + lane;
        bool v;
        if (mode == 0)      v = ((const uint8_t*) m)[idx] != 0;
        else if (mode == 1) v = ((const uint32_t*)m)[idx] != 0u;
        else                v = ((const float*)   m)[idx] != 0.0f;
        unsigned w = __ballot_sync(0xffffffffu, v);
        if (lane == s) g_maskbits[base/32 + s] = w;
    }
}

// ---------------------------------------------------------------------------
// Fused feature maps. Per CTA: one (bh, 128-row tile).
// Chunked over the 256 hidden dim in 4 slabs of 64:
//   T1c = gelu(X @ W1[:,slab]);  acc2 += T1c @ W2[slab,:]
// Q: qf = |gelu(acc2)|
// K: tmp = |sD|*gelu(acc2); kf = |tmp + (tmp@Wint)*sD2|
// smem: Xs[128][68] W1s[64][68] W2s[64][68] T1s[128][68]  = 104448 B
// ---------------------------------------------------------------------------
template <bool KPATH>
__device__ __forceinline__ void fused_features(
    const float* __restrict__ X, const float* __restrict__ W1,
    const float* __restrict__ W2, const float* __restrict__ Wint,
    const float* __restrict__ sD, const float* __restrict__ sD2,
    float* __restrict__ outg)
{
    extern __shared__ float sm[];
    float* Xs  = sm;                  // 128*68
    float* W1s = Xs  + 128*68;        // 64*68
    float* W2s = W1s + 64*68;         // 64*68
    float* T1s = W2s + 64*68;         // 128*68

    int bh = blockIdx.y, b = bh >> 4, h = bh & 15;
    int m0 = blockIdx.x * 128;
    int tid = threadIdx.x;
    int warp = tid >> 5, lane = tid & 31, g = lane >> 2, tg = lane & 3;
    int wm = warp & 3, wn = warp >> 2;

    const float* Xb = X + ((size_t)(b*S_ + m0))*D_ + h*DH_;
    for (int idx = tid; idx < 128*64; idx += 256) {
        int r = idx >> 6, d = idx & 63;
        Xs[r*68 + d] = to_tf32(Xb[(size_t)r*D_ + d]);
    }

    const float* W1h = W1 + (size_t)h*DH_*DHID_;
    const float* W2h = W2 + (size_t)h*DHID_*DKER_;

    float acc2[8][4];
    #pragma unroll
    for (int j=0;j<8;j++) for (int c=0;c<4;c++) acc2[j][c]=0.f;

    for (int c0 = 0; c0 < 4; c0++) {
        int n0 = c0*64;
        // W1 slab [n][k]
        for (int idx = tid; idx < 64*64; idx += 256) {
            int k = idx >> 6, n = idx & 63;
            W1s[n*68 + k] = to_tf32(W1h[(size_t)k*DHID_ + n0 + n]);
        }
        __syncthreads();   // (A)

        // GEMM1: 128x64, K=64; warps 4x2, warp tile 32x32
        float acc1[2][4][4];
        #pragma unroll
        for (int i=0;i<2;i++) for (int j=0;j<4;j++) for (int c=0;c<4;c++) acc1[i][j][c]=0.f;
        #pragma unroll
        for (int k0=0;k0<64;k0+=8) {
            float a[2][4], bf[4][2];
            #pragma unroll
            for (int i=0;i<2;i++) {
                int rb = wm*32 + i*16;
                a[i][0] = Xs[(rb+g  )*68 + k0+tg  ];
                a[i][1] = Xs[(rb+g+8)*68 + k0+tg  ];
                a[i][2] = Xs[(rb+g  )*68 + k0+tg+4];
                a[i][3] = Xs[(rb+g+8)*68 + k0+tg+4];
            }
            #pragma unroll
            for (int j=0;j<4;j++) {
                int nb = wn*32 + j*8 + g;
                bf[j][0] = W1s[nb*68 + k0+tg  ];
                bf[j][1] = W1s[nb*68 + k0+tg+4];
            }
            #pragma unroll
            for (int i=0;i<2;i++)
                #pragma unroll
                for (int j=0;j<4;j++)
                    mma_tf32(acc1[i][j], a[i], bf[j]);
        }
        // gelu -> T1s (tf32)
        #pragma unroll
        for (int i=0;i<2;i++) {
            #pragma unroll
            for (int j=0;j<4;j++) {
                int rr = wm*32 + i*16 + g;
                int cc = wn*32 + j*8 + 2*tg;
                *(float2*)&T1s[rr*68 + cc] =
                    make_float2(to_tf32(gelu_t(acc1[i][j][0])), to_tf32(gelu_t(acc1[i][j][1])));
                *(float2*)&T1s[(rr+8)*68 + cc] =
                    make_float2(to_tf32(gelu_t(acc1[i][j][2])), to_tf32(gelu_t(acc1[i][j][3])));
            }
        }
        // W2 slab [n][k]
        for (int idx = tid; idx < 64*64; idx += 256) {
            int k = idx >> 6, n = idx & 63;
            W2s[n*68 + k] = to_tf32(W2h[(size_t)(n0 + k)*DKER_ + n]);
        }
        __syncthreads();   // (B)

        // GEMM2 accumulate: warp owns rows warp*16..+15, all 64 cols
        #pragma unroll
        for (int k0=0;k0<64;k0+=8) {
            float a[4], bf[8][2];
            int rb = warp*16;
            a[0] = T1s[(rb+g  )*68 + k0+tg  ];
            a[1] = T1s[(rb+g+8)*68 + k0+tg  ];
            a[2] = T1s[(rb+g  )*68 + k0+tg+4];
            a[3] = T1s[(rb+g+8)*68 + k0+tg+4];
            #pragma unroll
            for (int j=0;j<8;j++) {
                int nb = j*8+g;
                bf[j][0] = W2s[nb*68 + k0+tg  ];
                bf[j][1] = W2s[nb*68 + k0+tg+4];
            }
            #pragma unroll
            for (int j=0;j<8;j++) mma_tf32(acc2[j], a, bf[j]);
        }
    }

    float* outp = outg + ((size_t)bh*S_ + m0)*DKER_;

    if (!KPATH) {
        #pragma unroll
        for (int j=0;j<8;j++) {
            int rr = warp*16 + g, cc = j*8 + 2*tg;
            *(float2*)&outp[(size_t)rr*DKER_ + cc] =
                make_float2(fabsf(gelu_t(acc2[j][0])), fabsf(gelu_t(acc2[j][1])));
            *(float2*)&outp[(size_t)(rr+8)*DKER_ + cc] =
                make_float2(fabsf(gelu_t(acc2[j][2])), fabsf(gelu_t(acc2[j][3])));
        }
        return;
    }

    // K path tail: tmp -> T1s (raw f32), Wint pass, combine
    const float* sDh  = sD  + h*DKER_;
    const float* sD2h = sD2 + h*DKER_;
    __syncthreads();   // last GEMM2 readers done before overwriting T1s
    #pragma unroll
    for (int j=0;j<8;j++) {
        int rr = warp*16 + g, cc = j*8 + 2*tg;
        T1s[rr*68 + cc  ]     = fabsf(sDh[cc  ]) * gelu_t(acc2[j][0]);
        T1s[rr*68 + cc+1]     = fabsf(sDh[cc+1]) * gelu_t(acc2[j][1]);
        T1s[(rr+8)*68 + cc  ] = fabsf(sDh[cc  ]) * gelu_t(acc2[j][2]);
        T1s[(rr+8)*68 + cc+1] = fabsf(sDh[cc+1]) * gelu_t(acc2[j][3]);
    }
    // Wint -> W1s [n][k]
    const float* Wih = Wint + (size_t)(bh & 15)*DKER_*DKER_;
    for (int idx = tid; idx < 64*64; idx += 256) {
        int k = idx >> 6, n = idx & 63;
        W1s[n*68 + k] = to_tf32(Wih[(size_t)k*DKER_ + n]);
    }
    __syncthreads();

    float ac2[8][4];
    #pragma unroll
    for (int j=0;j<8;j++) for (int c=0;c<4;c++) ac2[j][c]=0.f;
    #pragma unroll
    for (int k0=0;k0<64;k0+=8) {
        float a[4], bf[8][2];
        int rb = warp*16;
        a[0] = to_tf32(T1s[(rb+g  )*68 + k0+tg  ]);
        a[1] = to_tf32(T1s[(rb+g+8)*68 + k0+tg  ]);
        a[2] = to_tf32(T1s[(rb+g  )*68 + k0+tg+4]);
        a[3] = to_tf32(T1s[(rb+g+8)*68 + k0+tg+4]);
        #pragma unroll
        for (int j=0;j<8;j++) {
            int nb = j*8+g;
            bf[j][0] = W1s[nb*68 + k0+tg  ];
            bf[j][1] = W1s[nb*68 + k0+tg+4];
        }
        #pragma unroll
        for (int j=0;j<8;j++) mma_tf32(ac2[j], a, bf[j]);
    }

    #pragma unroll
    for (int j=0;j<8;j++) {
        int rr = warp*16 + g, cc = j*8 + 2*tg;
        float t00 = T1s[rr*68 + cc  ],     t01 = T1s[rr*68 + cc+1];
        float t10 = T1s[(rr+8)*68 + cc],   t11 = T1s[(rr+8)*68 + cc+1];
        *(float2*)&outp[(size_t)rr*DKER_ + cc] =
            make_float2(fabsf(t00 + ac2[j][0]*sD2h[cc  ]),
                        fabsf(t01 + ac2[j][1]*sD2h[cc+1]));
        *(float2*)&outp[(size_t)(rr+8)*DKER_ + cc] =
            make_float2(fabsf(t10 + ac2[j][2]*sD2h[cc  ]),
                        fabsf(t11 + ac2[j][3]*sD2h[cc+1]));
    }
}

__global__ __launch_bounds__(256)
void fusedq_kernel(const float* __restrict__ X, const float* __restrict__ W1,
                   const float* __restrict__ W2) {
    fused_features<false>(X, W1, W2, nullptr, nullptr, nullptr, g_qf);
}
__global__ __launch_bounds__(256)
void fusedk_kernel(const float* __restrict__ X, const float* __restrict__ W1,
                   const float* __restrict__ W2, const float* __restrict__ Wint,
                   const float* __restrict__ sD, const float* __restrict__ sD2) {
    fused_features<true>(X, W1, W2, Wint, sD, sD2, g_kf);
}

// ---------------------------------------------------------------------------
// Attention, pipelined:
//   per tile t: [wait KV(t)] PV(t-1) | cp.async saw(t)->Ps | score MMA(t)
//               | cp.async KV(t+1) | wait saw | epilogue (in-place Ps RMW)
// smem: Qs[128*68] Ks[128*68] Vs[2][128*72] Ps[128*132] rowsum[128] = 211456 B
// ---------------------------------------------------------------------------
__global__ __launch_bounds__(256, 1)
void attn_kernel(const float* __restrict__ Vg,
                 const float* __restrict__ sp_lse, const float* __restrict__ saw,
                 float* __restrict__ outp) {
    extern __shared__ float sm[];
    float* Qs = sm;                    // 128*68
    float* Ks = Qs + 128*68;           // 128*68
    float* Vs = Ks + 128*68;           // 2 x 128*72
    float* Ps = Vs + 2*128*72;         // 128*132
    float* rowsum = Ps + 128*132;      // 128

    int bh = blockIdx.y, b = bh >> 4, h = bh & 15;
    int m0 = blockIdx.x * 128;
    int tid = threadIdx.x, warp = tid>>5, lane = tid&31, g = lane>>2, tg = lane&3;
    int wm = warp & 3, wn = warp >> 2;

    // Q tile (once)
    const float* qf = g_qf + ((size_t)bh*S_ + m0)*DKER_;
    for (int idx = tid; idx < 128*64; idx += 256) {
        int r = idx>>6, e = idx&63;
        Qs[r*68+e] = to_tf32(qf[(size_t)r*DKER_ + e]);
    }
    if (tid < 128) rowsum[tid] = 0.f;

    // prologue: K(0), V(0)
    {
        const char* kfsrc = (const char*)(g_kf + (size_t)bh*S_*DKER_);
        const char* vsrc  = (const char*)(Vg + (size_t)b*S_*D_ + h*DH_);
        #pragma unroll
        for (int c = 0; c < 8; c++) {
            int qi = tid + c*256, r = qi>>4, cc = qi&15;
            CPA16(smaddr(Ks + r*68) + cc*16, kfsrc + r*256 + cc*16);
            CPA16(smaddr(Vs + r*72) + cc*16, vsrc + (size_t)r*4096 + cc*16);
        }
        CPA_COMMIT();
    }

    float oacc[8][4];
    #pragma unroll
    for (int j=0;j<8;j++) for (int c=0;c<4;c++) oacc[j][c]=0.f;
    float rsl[2][2] = {{0.f,0.f},{0.f,0.f}};

    const float* sawb = saw + (size_t)bh*S_*S_;

    for (int t = 0; t < 16; t++) {
        int t0 = t*128;

        // mask word prefetch (8 words, L2-resident)
        uint32_t mw[2][2][2];
        #pragma unroll
        for (int i=0;i<2;i++)
            #pragma unroll
            for (int p=0;p<2;p++) {
                int row = m0 + wm*32 + i*16 + g + 8*p;
                size_t widx = ((size_t)b*S_ + row)*64 + (t0>>5) + wn*2;
                mw[i][p][0] = g_maskbits[widx];
                mw[i][p][1] = g_maskbits[widx+1];
            }

        // (a) K(t),V(t) ready; epilogue(t-1) stores visible
        CPA_WAIT(0);
        __syncthreads();

        // (b) PV(t-1)
        if (t > 0) {
            const float* Vb = Vs + ((t-1)&1)*(128*72);
            #pragma unroll
            for (int k0 = 0; k0 < 128; k0 += 8) {
                float a[4], bf[8][2];
                int rb = warp*16;
                a[0] = Ps[(rb+g  )*132 + k0+tg  ];
                a[1] = Ps[(rb+g+8)*132 + k0+tg  ];
                a[2] = Ps[(rb+g  )*132 + k0+tg+4];
                a[3] = Ps[(rb+g+8)*132 + k0+tg+4];
                #pragma unroll
                for (int j=0;j<8;j++) {
                    bf[j][0] = to_tf32(Vb[(k0+tg  )*72 + j*8+g]);
                    bf[j][1] = to_tf32(Vb[(k0+tg+4)*72 + j*8+g]);
                }
                #pragma unroll
                for (int j=0;j<8;j++) mma_tf32(oacc[j], a, bf[j]);
            }
        }
        // (c) Ps free
        __syncthreads();

        // (d) saw(t) -> Ps  (group A)
        {
            const float* srow = sawb + (size_t)m0*S_ + t0;
            #pragma unroll
            for (int c = 0; c < 16; c++) {
                int qi = tid + c*256, r = qi>>5, cc = qi&31;
                CPA16(smaddr(Ps + r*132) + cc*16,
                      (const char*)(srow + (size_t)r*S_) + cc*16);
            }
            CPA_COMMIT();
        }

        // (e) score MMA(t)
        float sacc[2][8][4];
        #pragma unroll
        for (int i=0;i<2;i++) for (int j=0;j<8;j++) for (int c=0;c<4;c++) sacc[i][j][c]=0.f;
        #pragma unroll
        for (int k0 = 0; k0 < 64; k0 += 8) {
            float a[2][4], bf[8][2];
            #pragma unroll
            for (int i=0;i<2;i++) {
                int rb = wm*32 + i*16;
                a[i][0] = Qs[(rb+g  )*68 + k0+tg  ];
                a[i][1] = Qs[(rb+g+8)*68 + k0+tg  ];
                a[i][2] = Qs[(rb+g  )*68 + k0+tg+4];
                a[i][3] = Qs[(rb+g+8)*68 + k0+tg+4];
            }
            #pragma unroll
            for (int j=0;j<8;j++) {
                int nb = wn*64 + j*8 + g;
                bf[j][0] = to_tf32(Ks[nb*68 + k0+tg  ]);
                bf[j][1] = to_tf32(Ks[nb*68 + k0+tg+4]);
            }
            #pragma unroll
            for (int i=0;i<2;i++)
                #pragma unroll
                for (int j=0;j<8;j++)
                    mma_tf32(sacc[i][j], a[i], bf[j]);
        }

        // (f) Ks readers done
        __syncthreads();

        // (g) K(t+1), V(t+1)  (group B — always committed)
        if (t < 15) {
            int tn = t0 + 128;
            const char* kfsrc = (const char*)(g_kf + ((size_t)bh*S_ + tn)*DKER_);
            const char* vsrc  = (const char*)(Vg + ((size_t)(b*S_ + tn))*D_ + h*DH_);
            float* vdst = Vs + ((t+1)&1)*(128*72);
            #pragma unroll
            for (int c = 0; c < 8; c++) {
                int qi = tid + c*256, r = qi>>4, cc = qi&15;
                CPA16(smaddr(Ks + r*68) + cc*16, kfsrc + r*256 + cc*16);
                CPA16(smaddr(vdst + r*72) + cc*16, vsrc + (size_t)r*4096 + cc*16);
            }
        }
        CPA_COMMIT();

        // (h) saw arrived (group B may still fly)
        CPA_WAIT(1);
        __syncthreads();

        // (j) epilogue: in-place RMW of Ps
        #pragma unroll
        for (int i=0;i<2;i++) {
            int rl = wm*32 + i*16 + g;
            #pragma unroll
            for (int j=0;j<8;j++) {
                int cb = j*8 + 2*tg;
                int cl = wn*64 + cb;
                int w = cb >> 5, bit = cb & 31;
                #pragma unroll
                for (int p=0;p<2;p++) {
                    int rr = rl + 8*p;
                    float2 sw = *(float2*)&Ps[rr*132 + cl];
                    uint32_t word = mw[i][p][w];
                    bool b0 = (word >> bit) & 1u;
                    bool b1 = (word >> (bit+1)) & 1u;
                    float s0v = sacc[i][j][2*p], s1v = sacc[i][j][2*p+1];
                    float n0 = b0 ? s0v + 1e-6f : __expf(sw.x);
                    float n1 = b1 ? s1v + 1e-6f : __expf(sw.y);
                    rsl[i][p] += b0 ? s0v : 0.f;
                    rsl[i][p] += b1 ? s1v : 0.f;
                    *(float2*)&Ps[rr*132 + cl] = make_float2(to_tf32(n0), to_tf32(n1));
                }
            }
        }
        // next iteration's (a) barrier publishes Ps for PV
    }

    __syncthreads();   // epilogue(15) visible
    // final PV(15), buffer parity 1
    {
        const float* Vb = Vs + (15&1)*(128*72);
        #pragma unroll
        for (int k0 = 0; k0 < 128; k0 += 8) {
            float a[4], bf[8][2];
            int rb = warp*16;
            a[0] = Ps[(rb+g  )*132 + k0+tg  ];
            a[1] = Ps[(rb+g+8)*132 + k0+tg  ];
            a[2] = Ps[(rb+g  )*132 + k0+tg+4];
            a[3] = Ps[(rb+g+8)*132 + k0+tg+4];
            #pragma unroll
            for (int j=0;j<8;j++) {
                bf[j][0] = to_tf32(Vb[(k0+tg  )*72 + j*8+g]);
                bf[j][1] = to_tf32(Vb[(k0+tg+4)*72 + j*8+g]);
            }
            #pragma unroll
            for (int j=0;j<8;j++) mma_tf32(oacc[j], a, bf[j]);
        }
    }

    // masked row-sum reduction
    #pragma unroll
    for (int i=0;i<2;i++)
        #pragma unroll
        for (int p=0;p<2;p++) {
            float v = rsl[i][p];
            v += __shfl_xor_sync(0xffffffffu, v, 1);
            v += __shfl_xor_sync(0xffffffffu, v, 2);
            if (tg == 0) atomicAdd(&rowsum[wm*32 + i*16 + g + 8*p], v);
        }
    __syncthreads();

    const float* spb = sp_lse + (size_t)bh*S_ + m0;
    float* ob = outp + ((size_t)(b*S_ + m0))*D_ + h*DH_;
    int r0 = warp*16 + g;
    float den0 = 1.0f / (rowsum[r0  ] + 1e-6f + __expf(spb[r0  ]));
    float den1 = 1.0f / (rowsum[r0+8] + 1e-6f + __expf(spb[r0+8]));
    #pragma unroll
    for (int j=0;j<8;j++) {
        int cc = j*8 + 2*tg;
        *(float2*)&ob[(size_t)r0*D_ + cc] =
            make_float2(oacc[j][0]*den0, oacc[j][1]*den0);
        *(float2*)&ob[(size_t)(r0+8)*D_ + cc] =
            make_float2(oacc[j][2]*den1, oacc[j][3]*den1);
    }
}

// ---------------------------------------------------------------------------
extern "C" void kernel_launch(void* const* d_in, const int* in_sizes, int n_in,
                              void* d_out, int out_size) {
    (void)in_sizes; (void)n_in; (void)out_size;
    const float*   q    = (const float*)d_in[1];
    const float*   k    = (const float*)d_in[2];
    const float*   v    = (const float*)d_in[3];
    const void*    mask = d_in[4];
    const float*   sp   = (const float*)d_in[5];
    const float*   saw  = (const float*)d_in[6];
    const float*   Wq1  = (const float*)d_in[8];
    const float*   Wk1  = (const float*)d_in[9];
    const float*   Wq2  = (const float*)d_in[10];
    const float*   Wk2  = (const float*)d_in[11];
    const float*   Wint = (const float*)d_in[12];
    const float*   sD   = (const float*)d_in[13];
    const float*   sD2  = (const float*)d_in[14];
    float* outp = (float*)d_out;

    const int SMEMF = (128*68 + 64*68 + 64*68 + 128*68) * 4;                 // 104448
    const int SMEMA = (128*68 + 128*68 + 2*128*72 + 128*132 + 128) * 4;      // 211456

    cudaFuncSetAttribute(fusedq_kernel, cudaFuncAttributeMaxDynamicSharedMemorySize, SMEMF);
    cudaFuncSetAttribute(fusedk_kernel, cudaFuncAttributeMaxDynamicSharedMemorySize, SMEMF);
    cudaFuncSetAttribute(attn_kernel,   cudaFuncAttributeMaxDynamicSharedMemorySize, SMEMA);

    detect_mask_kernel<<<1, 32>>>((const uint32_t*)mask);
    maskbits_kernel<<<1024, 256>>>(mask);
    fusedq_kernel<<<dim3(16, BH_), 256, SMEMF>>>(q, Wq1, Wq2);
    fusedk_kernel<<<dim3(16, BH_), 256, SMEMF>>>(k, Wk1, Wk2, Wint, sD, sD2);
    attn_kernel<<<dim3(16, BH_), 256, SMEMA>>>(v, sp, saw, outp);
}

// round 6
// speedup vs baseline: 1.8264x; 1.1405x over previous
#include <cuda_runtime.h>
#include <cuda_bf16.h>
#include <cstdint>

#define B_    2
#define S_    2048
#define H_    16
#define DH_   64
#define DHID_ 256
#define DKER_ 64
#define D_    1024
#define BH_   (B_*H_)

// Scratch (static device globals)
__device__ uint32_t g_qf_w[BH_*S_*32];      // 8 MB  |qf| bf16x2
__device__ uint32_t g_kf_w[BH_*S_*32];      // 8 MB  |kf| bf16x2
__device__ int      g_mask_mode;
__device__ uint32_t g_maskbits[B_*S_*S_/32];

__device__ __forceinline__ float to_tf32(float x) {
    uint32_t u;
    asm("cvt.rna.tf32.f32 %0, %1;" : "=r"(u) : "f"(x));
    return __uint_as_float(u);
}
__device__ __forceinline__ uint32_t packbf(float lo, float hi) {
    uint32_t r;
    asm("cvt.rn.bf16x2.f32 %0, %1, %2;" : "=r"(r) : "f"(hi), "f"(lo));
    return r;
}
__device__ __forceinline__ float gelu_t(float x) {
    float x3 = x * x * x;
    float t  = tanhf(0.7978845608028654f * (x + 0.044715f * x3));
    return 0.5f * x * (1.0f + t);
}
__device__ __forceinline__ void mma_tf32(float* c, const float* a, const float* b) {
    asm volatile(
        "mma.sync.aligned.m16n8k8.row.col.f32.tf32.tf32.f32 "
        "{%0,%1,%2,%3}, {%4,%5,%6,%7}, {%8,%9}, {%0,%1,%2,%3};\n"
        : "+f"(c[0]), "+f"(c[1]), "+f"(c[2]), "+f"(c[3])
        : "r"(__float_as_uint(a[0])), "r"(__float_as_uint(a[1])),
          "r"(__float_as_uint(a[2])), "r"(__float_as_uint(a[3])),
          "r"(__float_as_uint(b[0])), "r"(__float_as_uint(b[1])));
}
__device__ __forceinline__ void mma_bf16(float* c, const uint32_t* a, const uint32_t* b) {
    asm volatile(
        "mma.sync.aligned.m16n8k16.row.col.f32.bf16.bf16.f32 "
        "{%0,%1,%2,%3}, {%4,%5,%6,%7}, {%8,%9}, {%0,%1,%2,%3};\n"
        : "+f"(c[0]), "+f"(c[1]), "+f"(c[2]), "+f"(c[3])
        : "r"(a[0]), "r"(a[1]), "r"(a[2]), "r"(a[3]),
          "r"(b[0]), "r"(b[1]));
}
__device__ __forceinline__ uint32_t smaddr(const void* p) {
    return (uint32_t)__cvta_generic_to_shared(p);
}
#define CPA16(dst, src) \
    asm volatile("cp.async.cg.shared.global [%0], [%1], 16;\n" :: "r"(dst), "l"(src))
#define CPA_COMMIT() asm volatile("cp.async.commit_group;\n" ::: "memory")
#define CPA_WAIT(N)  asm volatile("cp.async.wait_group %0;\n" :: "n"(N) : "memory")

// ---------------------------------------------------------------------------
__global__ void detect_mask_kernel(const uint32_t* __restrict__ m) {
    if (threadIdx.x == 0 && blockIdx.x == 0) {
        int mode = 1;
        for (int i = 0; i < 1024; i++) {
            uint32_t w = m[(size_t)i * 2048];
            if (w == 0x3f800000u) { mode = 2; break; }
            if (w > 1u)           { mode = 0; break; }
        }
        g_mask_mode = mode;
    }
}

__global__ __launch_bounds__(256)
void maskbits_kernel(const void* __restrict__ m) {
    int mode = g_mask_mode;
    int warpg = (blockIdx.x * 256 + threadIdx.x) >> 5;
    int lane  = threadIdx.x & 31;
    size_t base = (size_t)warpg * 1024;
    #pragma unroll 4
    for (int s = 0; s < 32; s++) {
        size_t idx = base + (size_t)s * 32 + lane;
        bool v;
        if (mode == 0)      v = ((const uint8_t*) m)[idx] != 0;
        else if (mode == 1) v = ((const uint32_t*)m)[idx] != 0u;
        else                v = ((const float*)   m)[idx] != 0.0f;
        unsigned w = __ballot_sync(0xffffffffu, v);
        if (lane == s) g_maskbits[base/32 + s] = w;
    }
}

// ---------------------------------------------------------------------------
// Fused feature maps (tf32 internally, bf16 packed outputs)
// ---------------------------------------------------------------------------
template <bool KPATH>
__device__ __forceinline__ void fused_features(
    const float* __restrict__ X, const float* __restrict__ W1,
    const float* __restrict__ W2, const float* __restrict__ Wint,
    const float* __restrict__ sD, const float* __restrict__ sD2,
    uint32_t* __restrict__ outg)
{
    extern __shared__ float sm[];
    float* Xs  = sm;                  // 128*68
    float* W1s = Xs  + 128*68;        // 64*68
    float* W2s = W1s + 64*68;         // 64*68
    float* T1s = W2s + 64*68;         // 128*68

    int bh = blockIdx.y, b = bh >> 4, h = bh & 15;
    int m0 = blockIdx.x * 128;
    int tid = threadIdx.x;
    int warp = tid >> 5, lane = tid & 31, g = lane >> 2, tg = lane & 3;
    int wm = warp & 3, wn = warp >> 2;

    const float* Xb = X + ((size_t)(b*S_ + m0))*D_ + h*DH_;
    for (int idx = tid; idx < 128*64; idx += 256) {
        int r = idx >> 6, d = idx & 63;
        Xs[r*68 + d] = to_tf32(Xb[(size_t)r*D_ + d]);
    }

    const float* W1h = W1 + (size_t)h*DH_*DHID_;
    const float* W2h = W2 + (size_t)h*DHID_*DKER_;

    float acc2[8][4];
    #pragma unroll
    for (int j=0;j<8;j++) for (int c=0;c<4;c++) acc2[j][c]=0.f;

    for (int c0 = 0; c0 < 4; c0++) {
        int n0 = c0*64;
        for (int idx = tid; idx < 64*64; idx += 256) {
            int k = idx >> 6, n = idx & 63;
            W1s[n*68 + k] = to_tf32(W1h[(size_t)k*DHID_ + n0 + n]);
        }
        __syncthreads();

        float acc1[2][4][4];
        #pragma unroll
        for (int i=0;i<2;i++) for (int j=0;j<4;j++) for (int c=0;c<4;c++) acc1[i][j][c]=0.f;
        #pragma unroll
        for (int k0=0;k0<64;k0+=8) {
            float a[2][4], bf[4][2];
            #pragma unroll
            for (int i=0;i<2;i++) {
                int rb = wm*32 + i*16;
                a[i][0] = Xs[(rb+g  )*68 + k0+tg  ];
                a[i][1] = Xs[(rb+g+8)*68 + k0+tg  ];
                a[i][2] = Xs[(rb+g  )*68 + k0+tg+4];
                a[i][3] = Xs[(rb+g+8)*68 + k0+tg+4];
            }
            #pragma unroll
            for (int j=0;j<4;j++) {
                int nb = wn*32 + j*8 + g;
                bf[j][0] = W1s[nb*68 + k0+tg  ];
                bf[j][1] = W1s[nb*68 + k0+tg+4];
            }
            #pragma unroll
            for (int i=0;i<2;i++)
                #pragma unroll
                for (int j=0;j<4;j++)
                    mma_tf32(acc1[i][j], a[i], bf[j]);
        }
        #pragma unroll
        for (int i=0;i<2;i++) {
            #pragma unroll
            for (int j=0;j<4;j++) {
                int rr = wm*32 + i*16 + g;
                int cc = wn*32 + j*8 + 2*tg;
                *(float2*)&T1s[rr*68 + cc] =
                    make_float2(to_tf32(gelu_t(acc1[i][j][0])), to_tf32(gelu_t(acc1[i][j][1])));
                *(float2*)&T1s[(rr+8)*68 + cc] =
                    make_float2(to_tf32(gelu_t(acc1[i][j][2])), to_tf32(gelu_t(acc1[i][j][3])));
            }
        }
        for (int idx = tid; idx < 64*64; idx += 256) {
            int k = idx >> 6, n = idx & 63;
            W2s[n*68 + k] = to_tf32(W2h[(size_t)(n0 + k)*DKER_ + n]);
        }
        __syncthreads();

        #pragma unroll
        for (int k0=0;k0<64;k0+=8) {
            float a[4], bf[8][2];
            int rb = warp*16;
            a[0] = T1s[(rb+g  )*68 + k0+tg  ];
            a[1] = T1s[(rb+g+8)*68 + k0+tg  ];
            a[2] = T1s[(rb+g  )*68 + k0+tg+4];
            a[3] = T1s[(rb+g+8)*68 + k0+tg+4];
            #pragma unroll
            for (int j=0;j<8;j++) {
                int nb = j*8+g;
                bf[j][0] = W2s[nb*68 + k0+tg  ];
                bf[j][1] = W2s[nb*68 + k0+tg+4];
            }
            #pragma unroll
            for (int j=0;j<8;j++) mma_tf32(acc2[j], a, bf[j]);
        }
    }

    uint32_t* outw = outg + ((size_t)bh*S_ + m0)*32;

    if (!KPATH) {
        #pragma unroll
        for (int j=0;j<8;j++) {
            int rr = warp*16 + g, wi = j*4 + tg;
            outw[(size_t)rr*32 + wi] =
                packbf(fabsf(gelu_t(acc2[j][0])), fabsf(gelu_t(acc2[j][1])));
            outw[(size_t)(rr+8)*32 + wi] =
                packbf(fabsf(gelu_t(acc2[j][2])), fabsf(gelu_t(acc2[j][3])));
        }
        return;
    }

    const float* sDh  = sD  + h*DKER_;
    const float* sD2h = sD2 + h*DKER_;
    __syncthreads();
    #pragma unroll
    for (int j=0;j<8;j++) {
        int rr = warp*16 + g, cc = j*8 + 2*tg;
        T1s[rr*68 + cc  ]     = fabsf(sDh[cc  ]) * gelu_t(acc2[j][0]);
        T1s[rr*68 + cc+1]     = fabsf(sDh[cc+1]) * gelu_t(acc2[j][1]);
        T1s[(rr+8)*68 + cc  ] = fabsf(sDh[cc  ]) * gelu_t(acc2[j][2]);
        T1s[(rr+8)*68 + cc+1] = fabsf(sDh[cc+1]) * gelu_t(acc2[j][3]);
    }
    const float* Wih = Wint + (size_t)h*DKER_*DKER_;
    for (int idx = tid; idx < 64*64; idx += 256) {
        int k = idx >> 6, n = idx & 63;
        W1s[n*68 + k] = to_tf32(Wih[(size_t)k*DKER_ + n]);
    }
    __syncthreads();

    float ac2[8][4];
    #pragma unroll
    for (int j=0;j<8;j++) for (int c=0;c<4;c++) ac2[j][c]=0.f;
    #pragma unroll
    for (int k0=0;k0<64;k0+=8) {
        float a[4], bf[8][2];
        int rb = warp*16;
        a[0] = to_tf32(T1s[(rb+g  )*68 + k0+tg  ]);
        a[1] = to_tf32(T1s[(rb+g+8)*68 + k0+tg  ]);
        a[2] = to_tf32(T1s[(rb+g  )*68 + k0+tg+4]);
        a[3] = to_tf32(T1s[(rb+g+8)*68 + k0+tg+4]);
        #pragma unroll
        for (int j=0;j<8;j++) {
            int nb = j*8+g;
            bf[j][0] = W1s[nb*68 + k0+tg  ];
            bf[j][1] = W1s[nb*68 + k0+tg+4];
        }
        #pragma unroll
        for (int j=0;j<8;j++) mma_tf32(ac2[j], a, bf[j]);
    }

    #pragma unroll
    for (int j=0;j<8;j++) {
        int rr = warp*16 + g, cc = j*8 + 2*tg;
        int wi = j*4 + tg;
        float t00 = T1s[rr*68 + cc  ],     t01 = T1s[rr*68 + cc+1];
        float t10 = T1s[(rr+8)*68 + cc],   t11 = T1s[(rr+8)*68 + cc+1];
        outw[(size_t)rr*32 + wi] =
            packbf(fabsf(t00 + ac2[j][0]*sD2h[cc  ]),
                   fabsf(t01 + ac2[j][1]*sD2h[cc+1]));
        outw[(size_t)(rr+8)*32 + wi] =
            packbf(fabsf(t10 + ac2[j][2]*sD2h[cc  ]),
                   fabsf(t11 + ac2[j][3]*sD2h[cc+1]));
    }
}

__global__ __launch_bounds__(256)
void fusedq_kernel(const float* __restrict__ X, const float* __restrict__ W1,
                   const float* __restrict__ W2) {
    fused_features<false>(X, W1, W2, nullptr, nullptr, nullptr, g_qf_w);
}
__global__ __launch_bounds__(256)
void fusedk_kernel(const float* __restrict__ X, const float* __restrict__ W1,
                   const float* __restrict__ W2, const float* __restrict__ Wint,
                   const float* __restrict__ sD, const float* __restrict__ sD2) {
    fused_features<true>(X, W1, W2, Wint, sD, sD2, g_kf_w);
}

// ---------------------------------------------------------------------------
// Attention: scores bf16 (qf/kf bf16x2), P/V tf32. T-tile = 64, 2 CTAs/SM.
// Per tile t (Ps holds P(t-1) at loop top; KV(t) group pending):
//   WAIT(0) -> sync -> PV(t-1) -> sync -> issue saw(t)->Ps [A]
//   -> score MMA(t) -> issue KV(t+1) [B] -> WAIT(1) -> sync
//   -> epilogue RMW Ps (tf32) -> sync
// smem: Qs[128*36]w Ks[2*64*36]w Vs(f32)[2*64*72] Ps(f32)[128*68] rowsum[128]
// = 109056 B
// ---------------------------------------------------------------------------
__global__ __launch_bounds__(256, 2)
void attn_kernel(const float* __restrict__ Vg,
                 const float* __restrict__ sp_lse, const float* __restrict__ saw,
                 float* __restrict__ outp) {
    extern __shared__ uint32_t smw[];
    uint32_t* Qs = smw;                    // 128*36 (bf16x2)
    uint32_t* Ks = Qs + 128*36;            // 2*64*36 (bf16x2)
    float*    Vs = (float*)(Ks + 2*64*36); // 2*64*72 f32
    float*    Ps = Vs + 2*64*72;           // 128*68 f32 (saw/P in place)
    float* rowsum = Ps + 128*68;           // 128

    int bh = blockIdx.y, b = bh >> 4, h = bh & 15;
    int m0 = blockIdx.x * 128;
    int tid = threadIdx.x, warp = tid>>5, lane = tid&31, g = lane>>2, tg = lane&3;
    int wm = warp & 3, wn = warp >> 2;

    // Q tile (bf16 words)
    const uint32_t* qsrc = g_qf_w + ((size_t)bh*S_ + m0)*32;
    for (int idx = tid; idx < 4096; idx += 256) {
        int r = idx >> 5, c = idx & 31;
        Qs[r*36 + c] = qsrc[idx];
    }
    if (tid < 128) rowsum[tid] = 0.f;

    const char* kbase = (const char*)(g_kf_w + (size_t)bh*S_*32);
    const char* vbase = (const char*)(Vg + (size_t)b*S_*D_ + h*DH_);
    const char* sbase = (const char*)(saw + (size_t)bh*S_*S_ + (size_t)m0*S_);

    // prologue: KV(0) [group]
    {
        #pragma unroll
        for (int c2 = 0; c2 < 2; c2++) {
            int qi = tid + c2*256, r = qi >> 3, cc = qi & 7;
            CPA16(smaddr(Ks + r*36) + cc*16, kbase + (size_t)r*128 + cc*16);
        }
        #pragma unroll
        for (int c2 = 0; c2 < 4; c2++) {
            int qi = tid + c2*256, r = qi >> 4, cc = qi & 15;
            CPA16(smaddr(Vs + r*72) + cc*16, vbase + (size_t)r*4096 + cc*16);
        }
        CPA_COMMIT();
    }

    float oacc[8][4];
    #pragma unroll
    for (int j=0;j<8;j++) for (int c=0;c<4;c++) oacc[j][c]=0.f;
    float rsl[2][2] = {{0.f,0.f},{0.f,0.f}};

    for (int t = 0; t < 32; t++) {
        int pt = t & 1;

        // mask words (L2-resident)
        uint32_t mw[2][2];
        #pragma unroll
        for (int i=0;i<2;i++)
            #pragma unroll
            for (int p=0;p<2;p++) {
                int row = m0 + wm*32 + i*16 + g + 8*p;
                mw[i][p] = g_maskbits[((size_t)(b*S_ + row))*64 + t*2 + wn];
            }

        // (1) KV(t) ready
        CPA_WAIT(0);
        __syncthreads();

        // (2) PV(t-1): tf32, P from Ps, V from Vs(parity t-1)
        if (t > 0) {
            const float* Vb = Vs + (pt^1)*64*72;
            int rb = warp*16;
            #pragma unroll
            for (int k0 = 0; k0 < 64; k0 += 8) {
                float a[4], bf[8][2];
                a[0] = Ps[(rb+g  )*68 + k0+tg  ];
                a[1] = Ps[(rb+g+8)*68 + k0+tg  ];
                a[2] = Ps[(rb+g  )*68 + k0+tg+4];
                a[3] = Ps[(rb+g+8)*68 + k0+tg+4];
                #pragma unroll
                for (int j=0;j<8;j++) {
                    bf[j][0] = to_tf32(Vb[(k0+tg  )*72 + j*8+g]);
                    bf[j][1] = to_tf32(Vb[(k0+tg+4)*72 + j*8+g]);
                }
                #pragma unroll
                for (int j=0;j<8;j++) mma_tf32(oacc[j], a, bf[j]);
            }
        }
        // (3) Ps free
        __syncthreads();

        // (4) saw(t) -> Ps [group A]
        {
            const char* srow = sbase + (size_t)t*256;
            #pragma unroll
            for (int c2 = 0; c2 < 8; c2++) {
                int qi = tid + c2*256, r = qi >> 4, cc = qi & 15;
                CPA16(smaddr(Ps + r*68) + cc*16, srow + (size_t)r*S_*4 + cc*16);
            }
            CPA_COMMIT();
        }

        // (5) score MMA(t): bf16, [128 x 64]
        float sacc[2][4][4];
        #pragma unroll
        for (int i=0;i<2;i++) for (int j=0;j<4;j++) for (int c=0;c<4;c++) sacc[i][j][c]=0.f;
        {
            const uint32_t* Kb = Ks + pt*64*36;
            #pragma unroll
            for (int kw = 0; kw < 32; kw += 8) {
                uint32_t a[2][4], bf[4][2];
                #pragma unroll
                for (int i=0;i<2;i++) {
                    int rb = wm*32 + i*16;
                    a[i][0] = Qs[(rb+g  )*36 + kw+tg  ];
                    a[i][1] = Qs[(rb+g+8)*36 + kw+tg  ];
                    a[i][2] = Qs[(rb+g  )*36 + kw+tg+4];
                    a[i][3] = Qs[(rb+g+8)*36 + kw+tg+4];
                }
                #pragma unroll
                for (int j=0;j<4;j++) {
                    int nb = wn*32 + j*8 + g;
                    bf[j][0] = Kb[nb*36 + kw+tg  ];
                    bf[j][1] = Kb[nb*36 + kw+tg+4];
                }
                #pragma unroll
                for (int i=0;i<2;i++)
                    #pragma unroll
                    for (int j=0;j<4;j++)
                        mma_bf16(sacc[i][j], a[i], bf[j]);
            }
        }

        // (6) KV(t+1) [group B]  (double-buffered; safe after sync (3))
        if (t < 31) {
            size_t t0n = (size_t)(t+1)*64;
            uint32_t* Kd = Ks + (pt^1)*64*36;
            float*    Vd = Vs + (pt^1)*64*72;
            #pragma unroll
            for (int c2 = 0; c2 < 2; c2++) {
                int qi = tid + c2*256, r = qi >> 3, cc = qi & 7;
                CPA16(smaddr(Kd + r*36) + cc*16, kbase + (t0n + r)*128 + cc*16);
            }
            #pragma unroll
            for (int c2 = 0; c2 < 4; c2++) {
                int qi = tid + c2*256, r = qi >> 4, cc = qi & 15;
                CPA16(smaddr(Vd + r*72) + cc*16, vbase + (t0n + r)*4096 + cc*16);
            }
        }
        CPA_COMMIT();

        // (7) saw(t) arrived (KV(t+1) may still fly)
        CPA_WAIT(1);
        __syncthreads();

        // (8) epilogue: RMW Ps in place (tf32 f32)
        #pragma unroll
        for (int i=0;i<2;i++) {
            int rlb = wm*32 + i*16 + g;
            #pragma unroll
            for (int j=0;j<4;j++) {
                int cl = wn*32 + j*8 + 2*tg;
                int bit = j*8 + 2*tg;
                #pragma unroll
                for (int p=0;p<2;p++) {
                    int rr = rlb + 8*p;
                    float2 sw = *(float2*)&Ps[rr*68 + cl];
                    uint32_t word = mw[i][p];
                    bool b0 = (word >> bit) & 1u;
                    bool b1 = (word >> (bit+1)) & 1u;
                    float s0 = sacc[i][j][2*p], s1 = sacc[i][j][2*p+1];
                    float n0 = b0 ? s0 + 1e-6f : __expf(sw.x);
                    float n1 = b1 ? s1 + 1e-6f : __expf(sw.y);
                    rsl[i][p] += (b0 ? s0 : 0.f) + (b1 ? s1 : 0.f);
                    *(float2*)&Ps[rr*68 + cl] = make_float2(to_tf32(n0), to_tf32(n1));
                }
            }
        }
        // (9) Ps published for next iter's PV
        __syncthreads();
    }

    // final PV(31), V parity 1
    {
        const float* Vb = Vs + 1*64*72;
        int rb = warp*16;
        #pragma unroll
        for (int k0 = 0; k0 < 64; k0 += 8) {
            float a[4], bf[8][2];
            a[0] = Ps[(rb+g  )*68 + k0+tg  ];
            a[1] = Ps[(rb+g+8)*68 + k0+tg  ];
            a[2] = Ps[(rb+g  )*68 + k0+tg+4];
            a[3] = Ps[(rb+g+8)*68 + k0+tg+4];
            #pragma unroll
            for (int j=0;j<8;j++) {
                bf[j][0] = to_tf32(Vb[(k0+tg  )*72 + j*8+g]);
                bf[j][1] = to_tf32(Vb[(k0+tg+4)*72 + j*8+g]);
            }
            #pragma unroll
            for (int j=0;j<8;j++) mma_tf32(oacc[j], a, bf[j]);
        }
    }

    // masked row-sum reduction
    #pragma unroll
    for (int i=0;i<2;i++)
        #pragma unroll
        for (int p=0;p<2;p++) {
            float v = rsl[i][p];
            v += __shfl_xor_sync(0xffffffffu, v, 1);
            v += __shfl_xor_sync(0xffffffffu, v, 2);
            if (tg == 0) atomicAdd(&rowsum[wm*32 + i*16 + g + 8*p], v);
        }
    __syncthreads();

    const float* spb = sp_lse + (size_t)bh*S_ + m0;
    float* ob = outp + ((size_t)(b*S_ + m0))*D_ + h*DH_;
    int r0 = warp*16 + g;
    float den0 = 1.0f / (rowsum[r0  ] + 1e-6f + __expf(spb[r0  ]));
    float den1 = 1.0f / (rowsum[r0+8] + 1e-6f + __expf(spb[r0+8]));
    #pragma unroll
    for (int j=0;j<8;j++) {
        int cc = j*8 + 2*tg;
        *(float2*)&ob[(size_t)r0*D_ + cc] =
            make_float2(oacc[j][0]*den0, oacc[j][1]*den0);
        *(float2*)&ob[(size_t)(r0+8)*D_ + cc] =
            make_float2(oacc[j][2]*den1, oacc[j][3]*den1);
    }
}

// ---------------------------------------------------------------------------
extern "C" void kernel_launch(void* const* d_in, const int* in_sizes, int n_in,
                              void* d_out, int out_size) {
    (void)in_sizes; (void)n_in; (void)out_size;
    const float*   q    = (const float*)d_in[1];
    const float*   k    = (const float*)d_in[2];
    const float*   v    = (const float*)d_in[3];
    const void*    mask = d_in[4];
    const float*   sp   = (const float*)d_in[5];
    const float*   saw  = (const float*)d_in[6];
    const float*   Wq1  = (const float*)d_in[8];
    const float*   Wk1  = (const float*)d_in[9];
    const float*   Wq2  = (const float*)d_in[10];
    const float*   Wk2  = (const float*)d_in[11];
    const float*   Wint = (const float*)d_in[12];
    const float*   sD   = (const float*)d_in[13];
    const float*   sD2  = (const float*)d_in[14];
    float* outp = (float*)d_out;

    const int SMEMF = (128*68 + 64*68 + 64*68 + 128*68) * 4;                   // 104448
    const int SMEMA = (128*36 + 2*64*36 + 2*64*72 + 128*68 + 128) * 4;         // 109056

    cudaFuncSetAttribute(fusedq_kernel, cudaFuncAttributeMaxDynamicSharedMemorySize, SMEMF);
    cudaFuncSetAttribute(fusedk_kernel, cudaFuncAttributeMaxDynamicSharedMemorySize, SMEMF);
    cudaFuncSetAttribute(attn_kernel,   cudaFuncAttributeMaxDynamicSharedMemorySize, SMEMA);

    detect_mask_kernel<<<1, 32>>>((const uint32_t*)mask);
    maskbits_kernel<<<1024, 256>>>(mask);
    fusedq_kernel<<<dim3(16, BH_), 256, SMEMF>>>(q, Wq1, Wq2);
    fusedk_kernel<<<dim3(16, BH_), 256, SMEMF>>>(k, Wk1, Wk2, Wint, sD, sD2);
    attn_kernel<<<dim3(16, BH_), 256, SMEMA>>>(v, sp, saw, outp);
}